// round 1
// baseline (speedup 1.0000x reference)
#include <cuda_runtime.h>
#include <math.h>

#define BATCH 8
#define NPTS 2048

// Scratch (no allocation allowed in kernel_launch)
__device__ float g_S[BATCH][9];
__device__ float g_meanP[BATCH][3];
__device__ float g_meanQ[BATCH][3];

// ---------------------------------------------------------------------------
// Kernel 0: per-batch means of P and Q; also zero S accumulators.
// grid = BATCH, block = 256
// ---------------------------------------------------------------------------
__global__ void means_kernel(const float* __restrict__ P,
                             const float* __restrict__ Q) {
    int b = blockIdx.x;
    int tid = threadIdx.x;
    const float* Pb = P + (size_t)b * NPTS * 3;
    const float* Qb = Q + (size_t)b * NPTS * 3;

    float sp0 = 0.f, sp1 = 0.f, sp2 = 0.f;
    float sq0 = 0.f, sq1 = 0.f, sq2 = 0.f;
    for (int n = tid; n < NPTS; n += 256) {
        sp0 += Pb[n * 3 + 0]; sp1 += Pb[n * 3 + 1]; sp2 += Pb[n * 3 + 2];
        sq0 += Qb[n * 3 + 0]; sq1 += Qb[n * 3 + 1]; sq2 += Qb[n * 3 + 2];
    }

    __shared__ float red[6][256];
    red[0][tid] = sp0; red[1][tid] = sp1; red[2][tid] = sp2;
    red[3][tid] = sq0; red[4][tid] = sq1; red[5][tid] = sq2;
    __syncthreads();
    for (int off = 128; off > 0; off >>= 1) {
        if (tid < off) {
            #pragma unroll
            for (int k = 0; k < 6; k++) red[k][tid] += red[k][tid + off];
        }
        __syncthreads();
    }
    if (tid < 9) g_S[b][tid] = 0.f;
    if (tid == 0) {
        const float inv = 1.0f / (float)NPTS;
        g_meanP[b][0] = red[0][0] * inv;
        g_meanP[b][1] = red[1][0] * inv;
        g_meanP[b][2] = red[2][0] * inv;
        g_meanQ[b][0] = red[3][0] * inv;
        g_meanQ[b][1] = red[4][0] * inv;
        g_meanQ[b][2] = red[5][0] * inv;
    }
}

// ---------------------------------------------------------------------------
// Kernel 1: stream M once, accumulate S[b] = (M@P)^T @ (Q - meanQ).
// grid = (32, BATCH), block = 256 (8 warps). Each block handles 64 rows of M;
// each warp 8 rows. P (2048x3) lives transposed in SMEM for float4 LDS.
// ---------------------------------------------------------------------------
__global__ void __launch_bounds__(256, 4) smat_kernel(
    const float* __restrict__ P,
    const float* __restrict__ Q,
    const float* __restrict__ M) {
    int b = blockIdx.y;

    __shared__ float p0[NPTS], p1[NPTS], p2[NPTS];
    const float* Pb = P + (size_t)b * NPTS * 3;
    for (int m = threadIdx.x; m < NPTS; m += 256) {
        p0[m] = Pb[m * 3 + 0];
        p1[m] = Pb[m * 3 + 1];
        p2[m] = Pb[m * 3 + 2];
    }
    __syncthreads();

    float mq0 = g_meanQ[b][0], mq1 = g_meanQ[b][1], mq2 = g_meanQ[b][2];

    int warp = threadIdx.x >> 5;
    int lane = threadIdx.x & 31;
    const float* Mb = M + (size_t)b * NPTS * NPTS;
    const float* Qb = Q + (size_t)b * NPTS * 3;

    float acc[9];
    #pragma unroll
    for (int i = 0; i < 9; i++) acc[i] = 0.f;

    int row0 = blockIdx.x * 64 + warp * 8;
    for (int r = 0; r < 8; r++) {
        int n = row0 + r;
        const float4* Mrow = reinterpret_cast<const float4*>(Mb + (size_t)n * NPTS);
        float d0 = 0.f, d1 = 0.f, d2 = 0.f;
        #pragma unroll
        for (int it = 0; it < NPTS / 128; it++) {   // 16 iterations
            int m4 = it * 32 + lane;
            float4 mv = Mrow[m4];
            int m = m4 * 4;
            float4 a = *reinterpret_cast<const float4*>(&p0[m]);
            float4 bb = *reinterpret_cast<const float4*>(&p1[m]);
            float4 c = *reinterpret_cast<const float4*>(&p2[m]);
            d0 += mv.x * a.x  + mv.y * a.y  + mv.z * a.z  + mv.w * a.w;
            d1 += mv.x * bb.x + mv.y * bb.y + mv.z * bb.z + mv.w * bb.w;
            d2 += mv.x * c.x  + mv.y * c.y  + mv.z * c.z  + mv.w * c.w;
        }
        // warp reduce the three dots
        #pragma unroll
        for (int off = 16; off > 0; off >>= 1) {
            d0 += __shfl_xor_sync(0xffffffffu, d0, off);
            d1 += __shfl_xor_sync(0xffffffffu, d1, off);
            d2 += __shfl_xor_sync(0xffffffffu, d2, off);
        }
        if (lane == 0) {
            float q0 = Qb[n * 3 + 0] - mq0;
            float q1 = Qb[n * 3 + 1] - mq1;
            float q2 = Qb[n * 3 + 2] - mq2;
            acc[0] += d0 * q0; acc[1] += d0 * q1; acc[2] += d0 * q2;
            acc[3] += d1 * q0; acc[4] += d1 * q1; acc[5] += d1 * q2;
            acc[6] += d2 * q0; acc[7] += d2 * q1; acc[8] += d2 * q2;
        }
    }

    __shared__ float sacc[8][9];
    if (lane == 0) {
        #pragma unroll
        for (int i = 0; i < 9; i++) sacc[warp][i] = acc[i];
    }
    __syncthreads();
    if (threadIdx.x < 9) {
        float s = 0.f;
        #pragma unroll
        for (int w = 0; w < 8; w++) s += sacc[w][threadIdx.x];
        atomicAdd(&g_S[b][threadIdx.x], s);
    }
}

// ---------------------------------------------------------------------------
// Kernel 2: per-batch 3x3 polar decomposition (Newton, fp64) -> R, t.
// S = U Sigma V^T ; polar factor Qp = U V^T ; R = V U^T = Qp^T.
// t = meanQ - R @ meanP.
// Output layout: out[0..71] = R (B,3,3) row-major, out[72..95] = t (B,3).
// ---------------------------------------------------------------------------
__global__ void polar_kernel(float* __restrict__ out) {
    int b = threadIdx.x;
    if (b >= BATCH) return;

    double X[9];
    #pragma unroll
    for (int i = 0; i < 9; i++) X[i] = (double)g_S[b][i];

    #pragma unroll
    for (int it = 0; it < 14; it++) {
        double C[9];
        C[0] = X[4] * X[8] - X[5] * X[7];
        C[1] = X[5] * X[6] - X[3] * X[8];
        C[2] = X[3] * X[7] - X[4] * X[6];
        C[3] = X[2] * X[7] - X[1] * X[8];
        C[4] = X[0] * X[8] - X[2] * X[6];
        C[5] = X[1] * X[6] - X[0] * X[7];
        C[6] = X[1] * X[5] - X[2] * X[4];
        C[7] = X[2] * X[3] - X[0] * X[5];
        C[8] = X[0] * X[4] - X[1] * X[3];
        double det = X[0] * C[0] + X[1] * C[1] + X[2] * C[2];
        double ad = fabs(det);
        double g = 1.0 / cbrt(ad);            // |det|^{-1/3}
        double sgn = det >= 0.0 ? 1.0 : -1.0;
        double g2s = sgn * g * g;
        #pragma unroll
        for (int i = 0; i < 9; i++) X[i] = 0.5 * (g * X[i] + g2s * C[i]);
    }
    // X ~= Qp = U V^T (orthogonal).  R = Qp^T.
    double R[9];
    #pragma unroll
    for (int i = 0; i < 3; i++)
        #pragma unroll
        for (int j = 0; j < 3; j++)
            R[i * 3 + j] = X[j * 3 + i];

    double mp[3], mq[3];
    #pragma unroll
    for (int i = 0; i < 3; i++) { mp[i] = (double)g_meanP[b][i]; mq[i] = (double)g_meanQ[b][i]; }

    float* Rout = out + b * 9;
    float* tout = out + BATCH * 9 + b * 3;
    #pragma unroll
    for (int i = 0; i < 3; i++) {
        double ti = mq[i];
        #pragma unroll
        for (int j = 0; j < 3; j++) {
            Rout[i * 3 + j] = (float)R[i * 3 + j];
            ti -= R[i * 3 + j] * mp[j];
        }
        tout[i] = (float)ti;
    }
}

// ---------------------------------------------------------------------------
extern "C" void kernel_launch(void* const* d_in, const int* in_sizes, int n_in,
                              void* d_out, int out_size) {
    const float* P = (const float*)d_in[0];   // Ppc [8,2048,3]
    const float* Q = (const float*)d_in[1];   // Qpc [8,2048,3]
    const float* M = (const float*)d_in[2];   // M   [8,2048,2048]
    float* out = (float*)d_out;               // [72 R] + [24 t] = 96 floats

    means_kernel<<<BATCH, 256>>>(P, Q);
    smat_kernel<<<dim3(32, BATCH), 256>>>(P, Q, M);
    polar_kernel<<<1, 32>>>(out);
}

// round 2
// speedup vs baseline: 3.0311x; 3.0311x over previous
#include <cuda_runtime.h>
#include <math.h>

#define BATCH 8
#define NPTS 2048
#define GRIDX 128            // blocks per batch along rows
#define ROWS_PER_BLOCK 16    // 8 warps * 2 rows

// Scratch: per-block partials [T(9), v(3)] — every slot written every call,
// so no zero-init needed, no atomics.
__device__ float g_part[BATCH][GRIDX][12];

// ---------------------------------------------------------------------------
// Kernel 1: stream M once. For each row n: d = M[n,:] @ P (3-vector).
// Accumulate T = sum_n d_n (x) q_n  and  v = sum_n d_n   (q RAW, not centered).
// grid = (GRIDX, BATCH), block = 256. Each warp: 2 rows, interleaved for MLP.
// ---------------------------------------------------------------------------
__global__ void __launch_bounds__(256) smat_kernel(
    const float* __restrict__ P,
    const float* __restrict__ Q,
    const float* __restrict__ M) {
    const int b = blockIdx.y;

    __shared__ float p0[NPTS], p1[NPTS], p2[NPTS];
    {
        const float* Pb = P + (size_t)b * NPTS * 3;
        for (int i = threadIdx.x; i < NPTS * 3; i += 256) {
            float v = Pb[i];
            int pt = i / 3, c = i - pt * 3;
            float* dst = (c == 0) ? p0 : (c == 1) ? p1 : p2;
            dst[pt] = v;
        }
    }
    __syncthreads();

    const int warp = threadIdx.x >> 5;
    const int lane = threadIdx.x & 31;
    const float* Mb = M + (size_t)b * NPTS * NPTS;
    const float* Qb = Q + (size_t)b * NPTS * 3;

    const int n0 = blockIdx.x * ROWS_PER_BLOCK + warp * 2;
    const float4* R0 = reinterpret_cast<const float4*>(Mb + (size_t)n0 * NPTS);
    const float4* R1 = reinterpret_cast<const float4*>(Mb + (size_t)(n0 + 1) * NPTS);

    float d00 = 0.f, d01 = 0.f, d02 = 0.f;   // partial dot, row n0
    float d10 = 0.f, d11 = 0.f, d12 = 0.f;   // partial dot, row n0+1

    #pragma unroll 8
    for (int it = 0; it < NPTS / 128; it++) {     // 16 iterations
        int m4 = it * 32 + lane;
        float4 mv0 = __ldcs(&R0[m4]);             // streaming: no reuse of M
        float4 mv1 = __ldcs(&R1[m4]);
        int m = m4 * 4;
        float4 a  = *reinterpret_cast<const float4*>(&p0[m]);
        float4 bb = *reinterpret_cast<const float4*>(&p1[m]);
        float4 c  = *reinterpret_cast<const float4*>(&p2[m]);
        d00 += mv0.x * a.x  + mv0.y * a.y  + mv0.z * a.z  + mv0.w * a.w;
        d01 += mv0.x * bb.x + mv0.y * bb.y + mv0.z * bb.z + mv0.w * bb.w;
        d02 += mv0.x * c.x  + mv0.y * c.y  + mv0.z * c.z  + mv0.w * c.w;
        d10 += mv1.x * a.x  + mv1.y * a.y  + mv1.z * a.z  + mv1.w * a.w;
        d11 += mv1.x * bb.x + mv1.y * bb.y + mv1.z * bb.z + mv1.w * bb.w;
        d12 += mv1.x * c.x  + mv1.y * c.y  + mv1.z * c.z  + mv1.w * c.w;
    }

    // warp butterfly reduce the six dots
    #pragma unroll
    for (int off = 16; off > 0; off >>= 1) {
        d00 += __shfl_xor_sync(0xffffffffu, d00, off);
        d01 += __shfl_xor_sync(0xffffffffu, d01, off);
        d02 += __shfl_xor_sync(0xffffffffu, d02, off);
        d10 += __shfl_xor_sync(0xffffffffu, d10, off);
        d11 += __shfl_xor_sync(0xffffffffu, d11, off);
        d12 += __shfl_xor_sync(0xffffffffu, d12, off);
    }

    __shared__ float sacc[8][12];
    if (lane == 0) {
        float q00 = Qb[n0 * 3 + 0], q01 = Qb[n0 * 3 + 1], q02 = Qb[n0 * 3 + 2];
        float q10 = Qb[n0 * 3 + 3], q11 = Qb[n0 * 3 + 4], q12 = Qb[n0 * 3 + 5];
        sacc[warp][0] = d00 * q00 + d10 * q10;
        sacc[warp][1] = d00 * q01 + d10 * q11;
        sacc[warp][2] = d00 * q02 + d10 * q12;
        sacc[warp][3] = d01 * q00 + d11 * q10;
        sacc[warp][4] = d01 * q01 + d11 * q11;
        sacc[warp][5] = d01 * q02 + d11 * q12;
        sacc[warp][6] = d02 * q00 + d12 * q10;
        sacc[warp][7] = d02 * q01 + d12 * q11;
        sacc[warp][8] = d02 * q02 + d12 * q12;
        sacc[warp][9]  = d00 + d10;
        sacc[warp][10] = d01 + d11;
        sacc[warp][11] = d02 + d12;
    }
    __syncthreads();
    if (threadIdx.x < 12) {
        float s = 0.f;
        #pragma unroll
        for (int w = 0; w < 8; w++) s += sacc[w][threadIdx.x];
        g_part[b][blockIdx.x][threadIdx.x] = s;
    }
}

// ---------------------------------------------------------------------------
// Kernel 2: per-batch finish. grid = BATCH, block = 256.
// 1) reduce g_part -> T, v   2) means of P and Q   3) S = T - v (x) meanQ
// 4) fp32 Newton polar: S = U Sig V^T, Qp = U V^T, R = Qp^T = V U^T
// 5) t = meanQ - R @ meanP
// out[0..71] = R (B,3,3) row-major ; out[72..95] = t (B,3)
// ---------------------------------------------------------------------------
__global__ void __launch_bounds__(256) finish_kernel(
    const float* __restrict__ P,
    const float* __restrict__ Q,
    float* __restrict__ out) {
    const int b = blockIdx.x;
    const int tid = threadIdx.x;

    // --- reduce partials (128 x 12) ---
    __shared__ float red[128][12];
    if (tid < 128) {
        #pragma unroll
        for (int j = 0; j < 12; j++) red[tid][j] = g_part[b][tid][j];
    }
    __syncthreads();
    for (int off = 64; off > 0; off >>= 1) {
        if (tid < off) {
            #pragma unroll
            for (int j = 0; j < 12; j++) red[tid][j] += red[tid + off][j];
        }
        __syncthreads();
    }

    // --- means of P and Q ---
    const float* Pb = P + (size_t)b * NPTS * 3;
    const float* Qb = Q + (size_t)b * NPTS * 3;
    float sp0 = 0.f, sp1 = 0.f, sp2 = 0.f, sq0 = 0.f, sq1 = 0.f, sq2 = 0.f;
    for (int n = tid; n < NPTS; n += 256) {
        sp0 += Pb[n * 3 + 0]; sp1 += Pb[n * 3 + 1]; sp2 += Pb[n * 3 + 2];
        sq0 += Qb[n * 3 + 0]; sq1 += Qb[n * 3 + 1]; sq2 += Qb[n * 3 + 2];
    }
    __shared__ float red2[256][6];
    red2[tid][0] = sp0; red2[tid][1] = sp1; red2[tid][2] = sp2;
    red2[tid][3] = sq0; red2[tid][4] = sq1; red2[tid][5] = sq2;
    __syncthreads();
    for (int off = 128; off > 0; off >>= 1) {
        if (tid < off) {
            #pragma unroll
            for (int j = 0; j < 6; j++) red2[tid][j] += red2[tid + off][j];
        }
        __syncthreads();
    }

    if (tid != 0) return;

    const float inv = 1.0f / (float)NPTS;
    float mp0 = red2[0][0] * inv, mp1 = red2[0][1] * inv, mp2 = red2[0][2] * inv;
    float mq0 = red2[0][3] * inv, mq1 = red2[0][4] * inv, mq2 = red2[0][5] * inv;

    float v0 = red[0][9], v1 = red[0][10], v2 = red[0][11];
    float X[9];
    X[0] = red[0][0] - v0 * mq0; X[1] = red[0][1] - v0 * mq1; X[2] = red[0][2] - v0 * mq2;
    X[3] = red[0][3] - v1 * mq0; X[4] = red[0][4] - v1 * mq1; X[5] = red[0][5] - v1 * mq2;
    X[6] = red[0][6] - v2 * mq0; X[7] = red[0][7] - v2 * mq1; X[8] = red[0][8] - v2 * mq2;

    // Newton polar iteration (fp32), det-scaled:
    // X <- 0.5 * (g*X + sgn(det)*g^2*cof(X)),  g = |det|^(-1/3)
    #pragma unroll
    for (int it = 0; it < 16; it++) {
        float C[9];
        C[0] = X[4] * X[8] - X[5] * X[7];
        C[1] = X[5] * X[6] - X[3] * X[8];
        C[2] = X[3] * X[7] - X[4] * X[6];
        C[3] = X[2] * X[7] - X[1] * X[8];
        C[4] = X[0] * X[8] - X[2] * X[6];
        C[5] = X[1] * X[6] - X[0] * X[7];
        C[6] = X[1] * X[5] - X[2] * X[4];
        C[7] = X[2] * X[3] - X[0] * X[5];
        C[8] = X[0] * X[4] - X[1] * X[3];
        float det = X[0] * C[0] + X[1] * C[1] + X[2] * C[2];
        float g = rcbrtf(fabsf(det));            // |det|^{-1/3}
        float g2s = copysignf(g * g, det);
        #pragma unroll
        for (int i = 0; i < 9; i++) X[i] = 0.5f * (g * X[i] + g2s * C[i]);
    }

    // R = Qp^T
    float R[9];
    #pragma unroll
    for (int i = 0; i < 3; i++)
        #pragma unroll
        for (int j = 0; j < 3; j++)
            R[i * 3 + j] = X[j * 3 + i];

    float* Rout = out + b * 9;
    float* tout = out + BATCH * 9 + b * 3;
    float mp[3] = {mp0, mp1, mp2};
    float mq[3] = {mq0, mq1, mq2};
    #pragma unroll
    for (int i = 0; i < 3; i++) {
        float ti = mq[i];
        #pragma unroll
        for (int j = 0; j < 3; j++) {
            Rout[i * 3 + j] = R[i * 3 + j];
            ti -= R[i * 3 + j] * mp[j];
        }
        tout[i] = ti;
    }
}

// ---------------------------------------------------------------------------
extern "C" void kernel_launch(void* const* d_in, const int* in_sizes, int n_in,
                              void* d_out, int out_size) {
    const float* P = (const float*)d_in[0];   // Ppc [8,2048,3]
    const float* Q = (const float*)d_in[1];   // Qpc [8,2048,3]
    const float* M = (const float*)d_in[2];   // M   [8,2048,2048]
    float* out = (float*)d_out;               // 72 R + 24 t

    smat_kernel<<<dim3(GRIDX, BATCH), 256>>>(P, Q, M);
    finish_kernel<<<BATCH, 256>>>(P, Q, out);
}

// round 3
// speedup vs baseline: 3.1766x; 1.0480x over previous
#include <cuda_runtime.h>
#include <math.h>

#define BATCH 8
#define NPTS 2048
#define GRIDX 128            // blocks per batch along rows
#define ROWS_PER_BLOCK 16    // 8 warps * 2 rows

// Per-block partials [T(9), v(3)] and completion counters.
__device__ float g_part[BATCH][GRIDX][12];
__device__ unsigned int g_count[BATCH];   // zero-initialized; reset each call

// ---------------------------------------------------------------------------
// Single fused kernel. grid = (GRIDX, BATCH), block = 256 (8 warps).
// Phase 1: stream M, per-block partials of T = sum d_n (x) q_n, v = sum d_n.
// Phase 2: last block per batch reduces partials, computes means, S, polar, out.
// ---------------------------------------------------------------------------
__global__ void __launch_bounds__(256) fused_kernel(
    const float* __restrict__ P,
    const float* __restrict__ Q,
    const float* __restrict__ M,
    float* __restrict__ out) {
    const int b = blockIdx.y;
    const int tid = threadIdx.x;
    const int warp = tid >> 5;
    const int lane = tid & 31;

    __shared__ float p0[NPTS], p1[NPTS], p2[NPTS];
    __shared__ float sacc[8][12];
    __shared__ float warpSums[8][6];
    __shared__ float sTv[12];
    __shared__ int sIsLast;

    const float* Pb = P + (size_t)b * NPTS * 3;
    const float* Qb = Q + (size_t)b * NPTS * 3;

    for (int i = tid; i < NPTS * 3; i += 256) {
        float v = Pb[i];
        int pt = i / 3, c = i - pt * 3;
        float* dst = (c == 0) ? p0 : (c == 1) ? p1 : p2;
        dst[pt] = v;
    }
    __syncthreads();

    // ---------------- Phase 1: stream 16 rows of M ----------------
    const float* Mb = M + (size_t)b * NPTS * NPTS;
    const int n0 = blockIdx.x * ROWS_PER_BLOCK + warp * 2;
    const float4* R0 = reinterpret_cast<const float4*>(Mb + (size_t)n0 * NPTS);
    const float4* R1 = reinterpret_cast<const float4*>(Mb + (size_t)(n0 + 1) * NPTS);

    float d00 = 0.f, d01 = 0.f, d02 = 0.f;
    float d10 = 0.f, d11 = 0.f, d12 = 0.f;

    #pragma unroll 8
    for (int it = 0; it < NPTS / 128; it++) {     // 16 iterations
        int m4 = it * 32 + lane;
        float4 mv0 = __ldcs(&R0[m4]);
        float4 mv1 = __ldcs(&R1[m4]);
        int m = m4 * 4;
        float4 a  = *reinterpret_cast<const float4*>(&p0[m]);
        float4 bb = *reinterpret_cast<const float4*>(&p1[m]);
        float4 c  = *reinterpret_cast<const float4*>(&p2[m]);
        d00 += mv0.x * a.x  + mv0.y * a.y  + mv0.z * a.z  + mv0.w * a.w;
        d01 += mv0.x * bb.x + mv0.y * bb.y + mv0.z * bb.z + mv0.w * bb.w;
        d02 += mv0.x * c.x  + mv0.y * c.y  + mv0.z * c.z  + mv0.w * c.w;
        d10 += mv1.x * a.x  + mv1.y * a.y  + mv1.z * a.z  + mv1.w * a.w;
        d11 += mv1.x * bb.x + mv1.y * bb.y + mv1.z * bb.z + mv1.w * bb.w;
        d12 += mv1.x * c.x  + mv1.y * c.y  + mv1.z * c.z  + mv1.w * c.w;
    }

    #pragma unroll
    for (int off = 16; off > 0; off >>= 1) {
        d00 += __shfl_xor_sync(0xffffffffu, d00, off);
        d01 += __shfl_xor_sync(0xffffffffu, d01, off);
        d02 += __shfl_xor_sync(0xffffffffu, d02, off);
        d10 += __shfl_xor_sync(0xffffffffu, d10, off);
        d11 += __shfl_xor_sync(0xffffffffu, d11, off);
        d12 += __shfl_xor_sync(0xffffffffu, d12, off);
    }

    if (lane == 0) {
        float q00 = Qb[n0 * 3 + 0], q01 = Qb[n0 * 3 + 1], q02 = Qb[n0 * 3 + 2];
        float q10 = Qb[n0 * 3 + 3], q11 = Qb[n0 * 3 + 4], q12 = Qb[n0 * 3 + 5];
        sacc[warp][0] = d00 * q00 + d10 * q10;
        sacc[warp][1] = d00 * q01 + d10 * q11;
        sacc[warp][2] = d00 * q02 + d10 * q12;
        sacc[warp][3] = d01 * q00 + d11 * q10;
        sacc[warp][4] = d01 * q01 + d11 * q11;
        sacc[warp][5] = d01 * q02 + d11 * q12;
        sacc[warp][6] = d02 * q00 + d12 * q10;
        sacc[warp][7] = d02 * q01 + d12 * q11;
        sacc[warp][8] = d02 * q02 + d12 * q12;
        sacc[warp][9]  = d00 + d10;
        sacc[warp][10] = d01 + d11;
        sacc[warp][11] = d02 + d12;
    }
    __syncthreads();
    if (tid < 12) {
        float s = 0.f;
        #pragma unroll
        for (int w = 0; w < 8; w++) s += sacc[w][tid];
        g_part[b][blockIdx.x][tid] = s;
    }
    __threadfence();
    __syncthreads();

    // ---------------- Phase 2: last block of this batch finishes ----------------
    if (tid == 0) {
        unsigned int old = atomicAdd(&g_count[b], 1u);
        sIsLast = (old == GRIDX - 1u) ? 1 : 0;
    }
    __syncthreads();
    if (!sIsLast) return;
    __threadfence();   // acquire: make other blocks' g_part writes visible

    // --- means: P from smem, Q via float4 triples from global ---
    float sp0 = 0.f, sp1 = 0.f, sp2 = 0.f;
    for (int n = tid; n < NPTS; n += 256) {
        sp0 += p0[n]; sp1 += p1[n]; sp2 += p2[n];
    }
    float sq0 = 0.f, sq1 = 0.f, sq2 = 0.f;
    const float4* Q4 = reinterpret_cast<const float4*>(Qb);
    #pragma unroll
    for (int t = 0; t < 2; t++) {
        int tr = tid + t * 256;               // triple index, 512 total
        float4 A = Q4[tr * 3 + 0];
        float4 Bv = Q4[tr * 3 + 1];
        float4 C = Q4[tr * 3 + 2];
        sq0 += A.x + A.w + Bv.z + C.y;
        sq1 += A.y + Bv.x + Bv.w + C.z;
        sq2 += A.z + Bv.y + C.x + C.w;
    }
    #pragma unroll
    for (int off = 16; off > 0; off >>= 1) {
        sp0 += __shfl_xor_sync(0xffffffffu, sp0, off);
        sp1 += __shfl_xor_sync(0xffffffffu, sp1, off);
        sp2 += __shfl_xor_sync(0xffffffffu, sp2, off);
        sq0 += __shfl_xor_sync(0xffffffffu, sq0, off);
        sq1 += __shfl_xor_sync(0xffffffffu, sq1, off);
        sq2 += __shfl_xor_sync(0xffffffffu, sq2, off);
    }
    if (lane == 0) {
        warpSums[warp][0] = sp0; warpSums[warp][1] = sp1; warpSums[warp][2] = sp2;
        warpSums[warp][3] = sq0; warpSums[warp][4] = sq1; warpSums[warp][5] = sq2;
    }

    // --- warp 0 reduces the 128x12 partials ---
    if (warp == 0) {
        float Tv[12];
        #pragma unroll
        for (int j = 0; j < 12; j++) Tv[j] = 0.f;
        #pragma unroll
        for (int r = 0; r < 4; r++) {
            const float* row = g_part[b][lane + r * 32];
            #pragma unroll
            for (int j = 0; j < 12; j++) Tv[j] += row[j];
        }
        #pragma unroll
        for (int off = 16; off > 0; off >>= 1) {
            #pragma unroll
            for (int j = 0; j < 12; j++)
                Tv[j] += __shfl_xor_sync(0xffffffffu, Tv[j], off);
        }
        if (lane == 0) {
            #pragma unroll
            for (int j = 0; j < 12; j++) sTv[j] = Tv[j];
        }
    }
    __syncthreads();

    if (tid == 0) {
        // reset counter for next graph replay
        g_count[b] = 0u;

        float mS[6];
        #pragma unroll
        for (int j = 0; j < 6; j++) {
            float s = 0.f;
            #pragma unroll
            for (int w = 0; w < 8; w++) s += warpSums[w][j];
            mS[j] = s;
        }
        const float inv = 1.0f / (float)NPTS;
        float mp0 = mS[0] * inv, mp1 = mS[1] * inv, mp2 = mS[2] * inv;
        float mq0 = mS[3] * inv, mq1 = mS[4] * inv, mq2 = mS[5] * inv;

        float v0 = sTv[9], v1 = sTv[10], v2 = sTv[11];
        float X[9];
        X[0] = sTv[0] - v0 * mq0; X[1] = sTv[1] - v0 * mq1; X[2] = sTv[2] - v0 * mq2;
        X[3] = sTv[3] - v1 * mq0; X[4] = sTv[4] - v1 * mq1; X[5] = sTv[5] - v1 * mq2;
        X[6] = sTv[6] - v2 * mq0; X[7] = sTv[7] - v2 * mq1; X[8] = sTv[8] - v2 * mq2;

        // Newton polar iteration (det-scaled): X -> 0.5*(g*X + sgn*g^2*cof(X))
        #pragma unroll
        for (int it = 0; it < 12; it++) {
            float C[9];
            C[0] = X[4] * X[8] - X[5] * X[7];
            C[1] = X[5] * X[6] - X[3] * X[8];
            C[2] = X[3] * X[7] - X[4] * X[6];
            C[3] = X[2] * X[7] - X[1] * X[8];
            C[4] = X[0] * X[8] - X[2] * X[6];
            C[5] = X[1] * X[6] - X[0] * X[7];
            C[6] = X[1] * X[5] - X[2] * X[4];
            C[7] = X[2] * X[3] - X[0] * X[5];
            C[8] = X[0] * X[4] - X[1] * X[3];
            float det = X[0] * C[0] + X[1] * C[1] + X[2] * C[2];
            float g = rcbrtf(fabsf(det));
            float g2s = copysignf(g * g, det);
            #pragma unroll
            for (int i = 0; i < 9; i++) X[i] = 0.5f * (g * X[i] + g2s * C[i]);
        }

        float R[9];
        #pragma unroll
        for (int i = 0; i < 3; i++)
            #pragma unroll
            for (int j = 0; j < 3; j++)
                R[i * 3 + j] = X[j * 3 + i];

        float* Rout = out + b * 9;
        float* tout = out + BATCH * 9 + b * 3;
        float mp[3] = {mp0, mp1, mp2};
        float mq[3] = {mq0, mq1, mq2};
        #pragma unroll
        for (int i = 0; i < 3; i++) {
            float ti = mq[i];
            #pragma unroll
            for (int j = 0; j < 3; j++) {
                Rout[i * 3 + j] = R[i * 3 + j];
                ti -= R[i * 3 + j] * mp[j];
            }
            tout[i] = ti;
        }
    }
}

// ---------------------------------------------------------------------------
extern "C" void kernel_launch(void* const* d_in, const int* in_sizes, int n_in,
                              void* d_out, int out_size) {
    const float* P = (const float*)d_in[0];   // Ppc [8,2048,3]
    const float* Q = (const float*)d_in[1];   // Qpc [8,2048,3]
    const float* M = (const float*)d_in[2];   // M   [8,2048,2048]
    float* out = (float*)d_out;               // 72 R + 24 t

    fused_kernel<<<dim3(GRIDX, BATCH), 256>>>(P, Q, M, out);
}

// round 4
// speedup vs baseline: 3.3721x; 1.0615x over previous
#include <cuda_runtime.h>
#include <math.h>

#define BATCH 8
#define NPTS 2048
#define GRIDX 64             // blocks per batch along rows
#define ROWS_PER_BLOCK 32    // 8 warps * 4 rows

// Per-block partials [T(9), v(3)] and completion counters.
__device__ float g_part[BATCH][GRIDX][12];
__device__ unsigned int g_count[BATCH];   // zero-initialized; reset each call

// ---------------------------------------------------------------------------
// Single fused kernel. grid = (GRIDX, BATCH), block = 256 (8 warps).
// Each warp streams 4 rows of M interleaved (4 independent LDG.128 / iter).
// Phase 2: last block per batch reduces partials, computes means, S, polar.
// ---------------------------------------------------------------------------
__global__ void __launch_bounds__(256, 5) fused_kernel(
    const float* __restrict__ P,
    const float* __restrict__ Q,
    const float* __restrict__ M,
    float* __restrict__ out) {
    const int b = blockIdx.y;
    const int tid = threadIdx.x;
    const int warp = tid >> 5;
    const int lane = tid & 31;

    __shared__ float p0[NPTS], p1[NPTS], p2[NPTS];
    __shared__ float sacc[8][12];
    __shared__ float warpSums[8][6];
    __shared__ float sTv[12];
    __shared__ int sIsLast;

    const float* Pb = P + (size_t)b * NPTS * 3;
    const float* Qb = Q + (size_t)b * NPTS * 3;

    for (int i = tid; i < NPTS * 3; i += 256) {
        float v = Pb[i];
        int pt = i / 3, c = i - pt * 3;
        float* dst = (c == 0) ? p0 : (c == 1) ? p1 : p2;
        dst[pt] = v;
    }
    __syncthreads();

    // ---------------- Phase 1: stream 4 rows of M per warp ----------------
    const float* Mb = M + (size_t)b * NPTS * NPTS;
    const int n0 = blockIdx.x * ROWS_PER_BLOCK + warp * 4;
    // single base pointer; rows at compile-time byte offsets 0/8K/16K/24K
    const float4* Rbase = reinterpret_cast<const float4*>(Mb + (size_t)n0 * NPTS);

    float d0x = 0.f, d0y = 0.f, d0z = 0.f;
    float d1x = 0.f, d1y = 0.f, d1z = 0.f;
    float d2x = 0.f, d2y = 0.f, d2z = 0.f;
    float d3x = 0.f, d3y = 0.f, d3z = 0.f;

    #pragma unroll 4
    for (int it = 0; it < NPTS / 128; it++) {     // 16 iterations
        int m4 = it * 32 + lane;
        float4 mv0 = __ldcs(&Rbase[m4]);                        // row n0
        float4 mv1 = __ldcs(&Rbase[m4 + 1 * (NPTS / 4)]);       // row n0+1
        float4 mv2 = __ldcs(&Rbase[m4 + 2 * (NPTS / 4)]);       // row n0+2
        float4 mv3 = __ldcs(&Rbase[m4 + 3 * (NPTS / 4)]);       // row n0+3
        int m = m4 * 4;
        float4 a  = *reinterpret_cast<const float4*>(&p0[m]);
        float4 bb = *reinterpret_cast<const float4*>(&p1[m]);
        float4 c  = *reinterpret_cast<const float4*>(&p2[m]);
        d0x += mv0.x * a.x  + mv0.y * a.y  + mv0.z * a.z  + mv0.w * a.w;
        d0y += mv0.x * bb.x + mv0.y * bb.y + mv0.z * bb.z + mv0.w * bb.w;
        d0z += mv0.x * c.x  + mv0.y * c.y  + mv0.z * c.z  + mv0.w * c.w;
        d1x += mv1.x * a.x  + mv1.y * a.y  + mv1.z * a.z  + mv1.w * a.w;
        d1y += mv1.x * bb.x + mv1.y * bb.y + mv1.z * bb.z + mv1.w * bb.w;
        d1z += mv1.x * c.x  + mv1.y * c.y  + mv1.z * c.z  + mv1.w * c.w;
        d2x += mv2.x * a.x  + mv2.y * a.y  + mv2.z * a.z  + mv2.w * a.w;
        d2y += mv2.x * bb.x + mv2.y * bb.y + mv2.z * bb.z + mv2.w * bb.w;
        d2z += mv2.x * c.x  + mv2.y * c.y  + mv2.z * c.z  + mv2.w * c.w;
        d3x += mv3.x * a.x  + mv3.y * a.y  + mv3.z * a.z  + mv3.w * a.w;
        d3y += mv3.x * bb.x + mv3.y * bb.y + mv3.z * bb.z + mv3.w * bb.w;
        d3z += mv3.x * c.x  + mv3.y * c.y  + mv3.z * c.z  + mv3.w * c.w;
    }

    #pragma unroll
    for (int off = 16; off > 0; off >>= 1) {
        d0x += __shfl_xor_sync(0xffffffffu, d0x, off);
        d0y += __shfl_xor_sync(0xffffffffu, d0y, off);
        d0z += __shfl_xor_sync(0xffffffffu, d0z, off);
        d1x += __shfl_xor_sync(0xffffffffu, d1x, off);
        d1y += __shfl_xor_sync(0xffffffffu, d1y, off);
        d1z += __shfl_xor_sync(0xffffffffu, d1z, off);
        d2x += __shfl_xor_sync(0xffffffffu, d2x, off);
        d2y += __shfl_xor_sync(0xffffffffu, d2y, off);
        d2z += __shfl_xor_sync(0xffffffffu, d2z, off);
        d3x += __shfl_xor_sync(0xffffffffu, d3x, off);
        d3y += __shfl_xor_sync(0xffffffffu, d3y, off);
        d3z += __shfl_xor_sync(0xffffffffu, d3z, off);
    }

    if (lane == 0) {
        const float* q = Qb + n0 * 3;
        float q0x = q[0], q0y = q[1],  q0z = q[2];
        float q1x = q[3], q1y = q[4],  q1z = q[5];
        float q2x = q[6], q2y = q[7],  q2z = q[8];
        float q3x = q[9], q3y = q[10], q3z = q[11];
        sacc[warp][0] = d0x * q0x + d1x * q1x + d2x * q2x + d3x * q3x;
        sacc[warp][1] = d0x * q0y + d1x * q1y + d2x * q2y + d3x * q3y;
        sacc[warp][2] = d0x * q0z + d1x * q1z + d2x * q2z + d3x * q3z;
        sacc[warp][3] = d0y * q0x + d1y * q1x + d2y * q2x + d3y * q3x;
        sacc[warp][4] = d0y * q0y + d1y * q1y + d2y * q2y + d3y * q3y;
        sacc[warp][5] = d0y * q0z + d1y * q1z + d2y * q2z + d3y * q3z;
        sacc[warp][6] = d0z * q0x + d1z * q1x + d2z * q2x + d3z * q3x;
        sacc[warp][7] = d0z * q0y + d1z * q1y + d2z * q2y + d3z * q3y;
        sacc[warp][8] = d0z * q0z + d1z * q1z + d2z * q2z + d3z * q3z;
        sacc[warp][9]  = d0x + d1x + d2x + d3x;
        sacc[warp][10] = d0y + d1y + d2y + d3y;
        sacc[warp][11] = d0z + d1z + d2z + d3z;
    }
    __syncthreads();
    if (tid < 12) {
        float s = 0.f;
        #pragma unroll
        for (int w = 0; w < 8; w++) s += sacc[w][tid];
        g_part[b][blockIdx.x][tid] = s;
    }
    __threadfence();
    __syncthreads();

    // ---------------- Phase 2: last block of this batch finishes ----------------
    if (tid == 0) {
        unsigned int old = atomicAdd(&g_count[b], 1u);
        sIsLast = (old == GRIDX - 1u) ? 1 : 0;
    }
    __syncthreads();
    if (!sIsLast) return;
    __threadfence();   // acquire: make other blocks' g_part writes visible

    // --- means: P from smem, Q via float4 triples from global ---
    float sp0 = 0.f, sp1 = 0.f, sp2 = 0.f;
    for (int n = tid; n < NPTS; n += 256) {
        sp0 += p0[n]; sp1 += p1[n]; sp2 += p2[n];
    }
    float sq0 = 0.f, sq1 = 0.f, sq2 = 0.f;
    const float4* Q4 = reinterpret_cast<const float4*>(Qb);
    #pragma unroll
    for (int t = 0; t < 2; t++) {
        int tr = tid + t * 256;               // triple index, 512 total
        float4 A = Q4[tr * 3 + 0];
        float4 Bv = Q4[tr * 3 + 1];
        float4 C = Q4[tr * 3 + 2];
        sq0 += A.x + A.w + Bv.z + C.y;
        sq1 += A.y + Bv.x + Bv.w + C.z;
        sq2 += A.z + Bv.y + C.x + C.w;
    }
    #pragma unroll
    for (int off = 16; off > 0; off >>= 1) {
        sp0 += __shfl_xor_sync(0xffffffffu, sp0, off);
        sp1 += __shfl_xor_sync(0xffffffffu, sp1, off);
        sp2 += __shfl_xor_sync(0xffffffffu, sp2, off);
        sq0 += __shfl_xor_sync(0xffffffffu, sq0, off);
        sq1 += __shfl_xor_sync(0xffffffffu, sq1, off);
        sq2 += __shfl_xor_sync(0xffffffffu, sq2, off);
    }
    if (lane == 0) {
        warpSums[warp][0] = sp0; warpSums[warp][1] = sp1; warpSums[warp][2] = sp2;
        warpSums[warp][3] = sq0; warpSums[warp][4] = sq1; warpSums[warp][5] = sq2;
    }

    // --- warp 0 reduces the 64x12 partials ---
    if (warp == 0) {
        float Tv[12];
        #pragma unroll
        for (int j = 0; j < 12; j++) Tv[j] = 0.f;
        #pragma unroll
        for (int r = 0; r < GRIDX / 32; r++) {
            const float* row = g_part[b][lane + r * 32];
            #pragma unroll
            for (int j = 0; j < 12; j++) Tv[j] += row[j];
        }
        #pragma unroll
        for (int off = 16; off > 0; off >>= 1) {
            #pragma unroll
            for (int j = 0; j < 12; j++)
                Tv[j] += __shfl_xor_sync(0xffffffffu, Tv[j], off);
        }
        if (lane == 0) {
            #pragma unroll
            for (int j = 0; j < 12; j++) sTv[j] = Tv[j];
        }
    }
    __syncthreads();

    if (tid == 0) {
        // reset counter for next graph replay
        g_count[b] = 0u;

        float mS[6];
        #pragma unroll
        for (int j = 0; j < 6; j++) {
            float s = 0.f;
            #pragma unroll
            for (int w = 0; w < 8; w++) s += warpSums[w][j];
            mS[j] = s;
        }
        const float inv = 1.0f / (float)NPTS;
        float mp0 = mS[0] * inv, mp1 = mS[1] * inv, mp2 = mS[2] * inv;
        float mq0 = mS[3] * inv, mq1 = mS[4] * inv, mq2 = mS[5] * inv;

        float v0 = sTv[9], v1 = sTv[10], v2 = sTv[11];
        float X[9];
        X[0] = sTv[0] - v0 * mq0; X[1] = sTv[1] - v0 * mq1; X[2] = sTv[2] - v0 * mq2;
        X[3] = sTv[3] - v1 * mq0; X[4] = sTv[4] - v1 * mq1; X[5] = sTv[5] - v1 * mq2;
        X[6] = sTv[6] - v2 * mq0; X[7] = sTv[7] - v2 * mq1; X[8] = sTv[8] - v2 * mq2;

        // Newton polar iteration (det-scaled): X -> 0.5*(g*X + sgn*g^2*cof(X))
        #pragma unroll
        for (int it = 0; it < 12; it++) {
            float C[9];
            C[0] = X[4] * X[8] - X[5] * X[7];
            C[1] = X[5] * X[6] - X[3] * X[8];
            C[2] = X[3] * X[7] - X[4] * X[6];
            C[3] = X[2] * X[7] - X[1] * X[8];
            C[4] = X[0] * X[8] - X[2] * X[6];
            C[5] = X[1] * X[6] - X[0] * X[7];
            C[6] = X[1] * X[5] - X[2] * X[4];
            C[7] = X[2] * X[3] - X[0] * X[5];
            C[8] = X[0] * X[4] - X[1] * X[3];
            float det = X[0] * C[0] + X[1] * C[1] + X[2] * C[2];
            float g = rcbrtf(fabsf(det));
            float g2s = copysignf(g * g, det);
            #pragma unroll
            for (int i = 0; i < 9; i++) X[i] = 0.5f * (g * X[i] + g2s * C[i]);
        }

        float R[9];
        #pragma unroll
        for (int i = 0; i < 3; i++)
            #pragma unroll
            for (int j = 0; j < 3; j++)
                R[i * 3 + j] = X[j * 3 + i];

        float* Rout = out + b * 9;
        float* tout = out + BATCH * 9 + b * 3;
        float mp[3] = {mp0, mp1, mp2};
        float mq[3] = {mq0, mq1, mq2};
        #pragma unroll
        for (int i = 0; i < 3; i++) {
            float ti = mq[i];
            #pragma unroll
            for (int j = 0; j < 3; j++) {
                Rout[i * 3 + j] = R[i * 3 + j];
                ti -= R[i * 3 + j] * mp[j];
            }
            tout[i] = ti;
        }
    }
}

// ---------------------------------------------------------------------------
extern "C" void kernel_launch(void* const* d_in, const int* in_sizes, int n_in,
                              void* d_out, int out_size) {
    const float* P = (const float*)d_in[0];   // Ppc [8,2048,3]
    const float* Q = (const float*)d_in[1];   // Qpc [8,2048,3]
    const float* M = (const float*)d_in[2];   // M   [8,2048,2048]
    float* out = (float*)d_out;               // 72 R + 24 t

    fused_kernel<<<dim3(GRIDX, BATCH), 256>>>(P, Q, M, out);
}